// round 2
// baseline (speedup 1.0000x reference)
#include <cuda_runtime.h>
#include <cuda_bf16.h>
#include <math.h>

// Problem constants
#define SEQ     2048
#define NEMBD   2560
#define NHEAD   32
#define HDIM    80
#define RD      32
#define OPSIZE  7680   // 3 * NEMBD

// Scratch (static device globals — allocation-free per harness rules)
__device__ float g_qkv[SEQ * OPSIZE];   // [t][0:2560]=Q, [2560:5120]=K, [5120:7680]=V
__device__ float g_att[SEQ * NEMBD];    // attention output, [t][h*80+d]

// ---------------------------------------------------------------------------
// Tiled SGEMM:  C[m,n] = sum_k A[m,k] * B[n,k] + bias[n]
// A: [M,K] row-major, B: [N,K] row-major (i.e., C = A @ B^T + bias)
// BM=BN=128, BK=16, 256 threads, 8x8 accum per thread.
// Requires M%128==0, N%128==0, K%16==0 (true for all calls here).
// ---------------------------------------------------------------------------
__global__ __launch_bounds__(256, 2)
void gemm_nt_bias(const float* __restrict__ A, const float* __restrict__ B,
                  const float* __restrict__ bias, float* __restrict__ C,
                  int M, int N, int K) {
    __shared__ float As[16][132];
    __shared__ float Bs[16][132];

    const int tid = threadIdx.x;
    const int tx = tid & 15;        // 0..15 -> n
    const int ty = tid >> 4;        // 0..15 -> m
    const int m0 = blockIdx.y * 128;
    const int n0 = blockIdx.x * 128;

    const int K4 = K >> 2;
    const float4* A4 = (const float4*)(A + (size_t)m0 * K);
    const float4* B4 = (const float4*)(B + (size_t)n0 * K);

    float acc[8][8];
    #pragma unroll
    for (int i = 0; i < 8; i++)
        #pragma unroll
        for (int j = 0; j < 8; j++) acc[i][j] = 0.f;

    for (int k0 = 0; k0 < K; k0 += 16) {
        // Load 128x16 tiles of A and B (512 float4 each), store transposed.
        #pragma unroll
        for (int it = 0; it < 2; it++) {
            int i = tid + it * 256;
            int row = i >> 2;
            int q   = i & 3;
            float4 va = A4[(size_t)row * K4 + (k0 >> 2) + q];
            As[q * 4 + 0][row] = va.x;
            As[q * 4 + 1][row] = va.y;
            As[q * 4 + 2][row] = va.z;
            As[q * 4 + 3][row] = va.w;
            float4 vb = B4[(size_t)row * K4 + (k0 >> 2) + q];
            Bs[q * 4 + 0][row] = vb.x;
            Bs[q * 4 + 1][row] = vb.y;
            Bs[q * 4 + 2][row] = vb.z;
            Bs[q * 4 + 3][row] = vb.w;
        }
        __syncthreads();

        #pragma unroll
        for (int k = 0; k < 16; k++) {
            float a[8], b[8];
            float4 a0 = *(const float4*)&As[k][ty * 8];
            float4 a1 = *(const float4*)&As[k][ty * 8 + 4];
            float4 b0 = *(const float4*)&Bs[k][tx * 8];
            float4 b1 = *(const float4*)&Bs[k][tx * 8 + 4];
            a[0]=a0.x; a[1]=a0.y; a[2]=a0.z; a[3]=a0.w;
            a[4]=a1.x; a[5]=a1.y; a[6]=a1.z; a[7]=a1.w;
            b[0]=b0.x; b[1]=b0.y; b[2]=b0.z; b[3]=b0.w;
            b[4]=b1.x; b[5]=b1.y; b[6]=b1.z; b[7]=b1.w;
            #pragma unroll
            for (int i = 0; i < 8; i++)
                #pragma unroll
                for (int j = 0; j < 8; j++)
                    acc[i][j] = fmaf(a[i], b[j], acc[i][j]);
        }
        __syncthreads();
    }

    // Epilogue: add bias, write 8x8 block with float4 stores.
    #pragma unroll
    for (int i = 0; i < 8; i++) {
        int m = m0 + ty * 8 + i;
        float* Crow = C + (size_t)m * N + n0 + tx * 8;
        const float* brow = bias + n0 + tx * 8;
        float4 c0, c1;
        c0.x = acc[i][0] + brow[0];
        c0.y = acc[i][1] + brow[1];
        c0.z = acc[i][2] + brow[2];
        c0.w = acc[i][3] + brow[3];
        c1.x = acc[i][4] + brow[4];
        c1.y = acc[i][5] + brow[5];
        c1.z = acc[i][6] + brow[6];
        c1.w = acc[i][7] + brow[7];
        *(float4*)(Crow)     = c0;
        *(float4*)(Crow + 4) = c1;
    }
}

// ---------------------------------------------------------------------------
// Partial RoPE (NOTE: reference has NO sign flip):
//   out[d]    = x[d]    * cos[d] + x[d+16] * sin[d]        (d < 16)
//   out[d+16] = x[d+16] * cos[d+16] + x[d] * sin[d+16]
// cos[d] == cos[d+16], sin[d] == sin[d+16] by construction, applied to Q and K.
// One thread per (t, h, d<16), handles the (d, d+16) pair for both Q and K.
// ---------------------------------------------------------------------------
__global__ void rope_kernel(float* __restrict__ qkv,
                            const float* __restrict__ cosT,
                            const float* __restrict__ sinT) {
    int idx = blockIdx.x * blockDim.x + threadIdx.x;
    if (idx >= SEQ * NHEAD * 16) return;
    int d = idx & 15;
    int h = (idx >> 4) & 31;
    int t = idx >> 9;

    float c  = cosT[t * RD + d];
    float s  = sinT[t * RD + d];
    float c2 = cosT[t * RD + d + 16];
    float s2 = sinT[t * RD + d + 16];

    float* q = qkv + (size_t)t * OPSIZE + h * HDIM;
    float x0 = q[d], x1 = q[d + 16];
    q[d]      = x0 * c  + x1 * s;
    q[d + 16] = x1 * c2 + x0 * s2;

    float* k = q + NEMBD;
    x0 = k[d]; x1 = k[d + 16];
    k[d]      = x0 * c  + x1 * s;
    k[d + 16] = x1 * c2 + x0 * s2;
}

// ---------------------------------------------------------------------------
// Flash-attention (fp32, causal). Grid: (q_block, head). 256 threads.
// BQ = BK = 64. Thread (ty,tx): S rows ty*4..+3, S cols tx*4..+3,
// O rows ty*4..+3, O cols tx*5..+4.
// Smem (dynamic, 81408 B):
//   Qs[80][68] transposed (pre-scaled), Ks[80][68] transposed,
//   Ss[64][68] probabilities, Vs[64][80].
// ---------------------------------------------------------------------------
__global__ __launch_bounds__(256, 2)
void flash_attn(const float* __restrict__ qkv, float* __restrict__ out) {
    extern __shared__ float sm[];
    float* Qs = sm;                 // [80][68]  Qs[d*68 + r]
    float* Ks = sm + 5440;          // [80][68]
    float* Ss = sm + 10880;         // [64][68]  Ss[r*68 + j]
    float* Vs = sm + 15232;         // [64][80]  Vs[r*80 + d]

    const int h  = blockIdx.y;
    const int qb = blockIdx.x;
    const int q0 = qb * 64;
    const int tid = threadIdx.x;
    const int tx = tid & 15;
    const int ty = tid >> 4;
    const int ty4 = ty * 4, tx4 = tx * 4, tx5 = tx * 5;

    const float scale = 0.11180339887498948f; // 1/sqrt(80)
    const float* Qg = qkv + h * HDIM;
    const float* Kg = qkv + NEMBD + h * HDIM;
    const float* Vg = qkv + 2 * NEMBD + h * HDIM;

    // Load Q tile (transposed, pre-scaled)
    for (int i = tid; i < 64 * 80; i += 256) {
        int r = i / 80, d = i % 80;
        Qs[d * 68 + r] = Qg[(size_t)(q0 + r) * OPSIZE + d] * scale;
    }

    float m_i[4], l_i[4], acc[4][5];
    #pragma unroll
    for (int i = 0; i < 4; i++) {
        m_i[i] = -1e30f; l_i[i] = 0.f;
        #pragma unroll
        for (int c = 0; c < 5; c++) acc[i][c] = 0.f;
    }

    const int ntiles = qb + 1;
    for (int tile = 0; tile < ntiles; tile++) {
        const int j0 = tile * 64;
        __syncthreads();  // protect Ks/Vs/Ss from prior iteration consumers
        for (int i = tid; i < 64 * 80; i += 256) {
            int r = i / 80, d = i % 80;
            Ks[d * 68 + r] = Kg[(size_t)(j0 + r) * OPSIZE + d];
            Vs[i]          = Vg[(size_t)(j0 + r) * OPSIZE + d];
        }
        __syncthreads();

        // S = (scale*Q) @ K^T  — 4x4 per thread
        float s[4][4];
        #pragma unroll
        for (int i = 0; i < 4; i++)
            #pragma unroll
            for (int j = 0; j < 4; j++) s[i][j] = 0.f;

        #pragma unroll 8
        for (int d = 0; d < 80; d++) {
            float4 qv = *(const float4*)&Qs[d * 68 + ty4];
            float4 kv = *(const float4*)&Ks[d * 68 + tx4];
            float qa[4] = {qv.x, qv.y, qv.z, qv.w};
            float ka[4] = {kv.x, kv.y, kv.z, kv.w};
            #pragma unroll
            for (int i = 0; i < 4; i++)
                #pragma unroll
                for (int j = 0; j < 4; j++)
                    s[i][j] = fmaf(qa[i], ka[j], s[i][j]);
        }

        // Causal mask (only the diagonal tile needs it)
        if (j0 == q0) {
            #pragma unroll
            for (int i = 0; i < 4; i++)
                #pragma unroll
                for (int j = 0; j < 4; j++)
                    if (tx4 + j > ty4 + i) s[i][j] = -1e30f;
        }

        // Online softmax per row (row = ty4+i, stats reduced over 16 tx lanes)
        #pragma unroll
        for (int i = 0; i < 4; i++) {
            float mx = fmaxf(fmaxf(s[i][0], s[i][1]), fmaxf(s[i][2], s[i][3]));
            #pragma unroll
            for (int off = 8; off >= 1; off >>= 1)
                mx = fmaxf(mx, __shfl_xor_sync(0xffffffffu, mx, off));
            float m_new = fmaxf(m_i[i], mx);
            float alpha = __expf(m_i[i] - m_new);
            float lp = 0.f;
            #pragma unroll
            for (int j = 0; j < 4; j++) {
                float p = __expf(s[i][j] - m_new);
                lp += p;
                Ss[(ty4 + i) * 68 + tx4 + j] = p;
            }
            #pragma unroll
            for (int off = 8; off >= 1; off >>= 1)
                lp += __shfl_xor_sync(0xffffffffu, lp, off);
            l_i[i] = l_i[i] * alpha + lp;
            m_i[i] = m_new;
            #pragma unroll
            for (int c = 0; c < 5; c++) acc[i][c] *= alpha;
        }
        __syncthreads();

        // O += P @ V
        #pragma unroll 4
        for (int j = 0; j < 64; j++) {
            float p[4];
            #pragma unroll
            for (int i = 0; i < 4; i++) p[i] = Ss[(ty4 + i) * 68 + j];
            #pragma unroll
            for (int c = 0; c < 5; c++) {
                float v = Vs[j * 80 + tx5 + c];
                #pragma unroll
                for (int i = 0; i < 4; i++)
                    acc[i][c] = fmaf(p[i], v, acc[i][c]);
            }
        }
    }

    // Normalize and write O
    #pragma unroll
    for (int i = 0; i < 4; i++) {
        float inv = 1.f / l_i[i];
        int r = q0 + ty4 + i;
        float* orow = out + (size_t)r * NEMBD + h * HDIM + tx5;
        #pragma unroll
        for (int c = 0; c < 5; c++) orow[c] = acc[i][c] * inv;
    }
}

// ---------------------------------------------------------------------------
// Launch
// ---------------------------------------------------------------------------
extern "C" void kernel_launch(void* const* d_in, const int* in_sizes, int n_in,
                              void* d_out, int out_size) {
    const float* hidden = (const float*)d_in[0];   // [1,2048,2560]
    const float* Wqkv_w = (const float*)d_in[1];   // [7680,2560]
    const float* Wqkv_b = (const float*)d_in[2];   // [7680]
    const float* out_w  = (const float*)d_in[3];   // [2560,2560]
    const float* out_b  = (const float*)d_in[4];   // [2560]
    const float* cosT   = (const float*)d_in[5];   // [2048,32]
    const float* sinT   = (const float*)d_in[6];   // [2048,32]
    float* out = (float*)d_out;                    // [1,2048,2560]

    float* qkv; cudaGetSymbolAddress((void**)&qkv, g_qkv);
    float* att; cudaGetSymbolAddress((void**)&att, g_att);

    // 1) QKV = H @ Wqkv^T + b
    {
        dim3 grid(OPSIZE / 128, SEQ / 128);
        gemm_nt_bias<<<grid, 256>>>(hidden, Wqkv_w, Wqkv_b, qkv,
                                    SEQ, OPSIZE, NEMBD);
    }

    // 2) Partial RoPE on Q and K (in place)
    {
        int total = SEQ * NHEAD * 16;
        rope_kernel<<<(total + 255) / 256, 256>>>(qkv, cosT, sinT);
    }

    // 3) Causal flash attention
    {
        const int smem = 81408;
        cudaFuncSetAttribute(flash_attn,
                             cudaFuncAttributeMaxDynamicSharedMemorySize, smem);
        dim3 grid(SEQ / 64, NHEAD);
        flash_attn<<<grid, 256, smem>>>(qkv, att);
    }

    // 4) out = att @ out_w^T + out_b
    {
        dim3 grid(NEMBD / 128, SEQ / 128);
        gemm_nt_bias<<<grid, 256>>>(att, out_w, out_b, out,
                                    SEQ, NEMBD, NEMBD);
    }
}

// round 8
// speedup vs baseline: 2.1009x; 2.1009x over previous
#include <cuda_runtime.h>
#include <cuda_bf16.h>
#include <math.h>
#include <stdint.h>

// Problem constants
#define SEQ     2048
#define NEMBD   2560
#define NHEAD   32
#define HDIM    80
#define RD      32
#define OPSIZE  7680   // 3 * NEMBD

// ---------------------------------------------------------------------------
// Static device scratch (allocation-free per harness rules)
// ---------------------------------------------------------------------------
__device__ float g_qkv[SEQ * OPSIZE];
__device__ float g_att[SEQ * NEMBD];

__device__ __nv_bfloat16 g_Hh[SEQ * NEMBD],    g_Hl[SEQ * NEMBD];
__device__ __nv_bfloat16 g_Wh[OPSIZE * NEMBD], g_Wl[OPSIZE * NEMBD];
__device__ __nv_bfloat16 g_Ch[SEQ * NEMBD],    g_Cl[SEQ * NEMBD];
__device__ __nv_bfloat16 g_Oh[NEMBD * NEMBD],  g_Ol[NEMBD * NEMBD];

// ---------------------------------------------------------------------------
// Helpers (base-target instructions only: cp.async / ldmatrix / mma.sync)
// ---------------------------------------------------------------------------
__device__ __forceinline__ uint32_t smem_u32(const void* p) {
    uint32_t a;
    asm("{ .reg .u64 t; cvta.to.shared.u64 t, %1; cvt.u32.u64 %0, t; }"
        : "=r"(a) : "l"(p));
    return a;
}
#define SWZ128(o) ((o) ^ (((o) >> 3) & 0x70))

__device__ __forceinline__ void cp_async16(uint32_t s, const void* g) {
    asm volatile("cp.async.cg.shared.global [%0], [%1], 16;\n" :: "r"(s), "l"(g));
}

__device__ __forceinline__ void ldsm4(uint32_t* r, uint32_t a) {
    asm volatile("ldmatrix.sync.aligned.m8n8.x4.shared.b16 {%0,%1,%2,%3}, [%4];"
        : "=r"(r[0]), "=r"(r[1]), "=r"(r[2]), "=r"(r[3]) : "r"(a));
}

__device__ __forceinline__ void mma16816(float* d, const uint32_t* a, const uint32_t* b) {
    asm volatile(
        "mma.sync.aligned.m16n8k16.row.col.f32.bf16.bf16.f32 "
        "{%0,%1,%2,%3}, {%4,%5,%6,%7}, {%8,%9}, {%0,%1,%2,%3};"
        : "+f"(d[0]), "+f"(d[1]), "+f"(d[2]), "+f"(d[3])
        : "r"(a[0]), "r"(a[1]), "r"(a[2]), "r"(a[3]), "r"(b[0]), "r"(b[1]));
}

// ---------------------------------------------------------------------------
// fp32 -> bf16 hi/lo splitter
// ---------------------------------------------------------------------------
__global__ void cvt_split(const float* __restrict__ x,
                          __nv_bfloat16* __restrict__ hi,
                          __nv_bfloat16* __restrict__ lo, int n4) {
    int i = blockIdx.x * blockDim.x + threadIdx.x;
    if (i >= n4) return;
    float4 v = ((const float4*)x)[i];
    __nv_bfloat16 h0 = __float2bfloat16(v.x);
    __nv_bfloat16 h1 = __float2bfloat16(v.y);
    __nv_bfloat16 h2 = __float2bfloat16(v.z);
    __nv_bfloat16 h3 = __float2bfloat16(v.w);
    __nv_bfloat16 l0 = __float2bfloat16(v.x - __bfloat162float(h0));
    __nv_bfloat16 l1 = __float2bfloat16(v.y - __bfloat162float(h1));
    __nv_bfloat16 l2 = __float2bfloat16(v.z - __bfloat162float(h2));
    __nv_bfloat16 l3 = __float2bfloat16(v.w - __bfloat162float(h3));
    __nv_bfloat162* hp = (__nv_bfloat162*)(hi + i * 4);
    __nv_bfloat162* lp = (__nv_bfloat162*)(lo + i * 4);
    hp[0] = __nv_bfloat162(h0, h1); hp[1] = __nv_bfloat162(h2, h3);
    lp[0] = __nv_bfloat162(l0, l1); lp[1] = __nv_bfloat162(l2, l3);
}

// ---------------------------------------------------------------------------
// HMMA bf16x3 GEMM:  C[m,n] = sum_k A[m,k]*B[n,k] + bias[n]
// A = Ah+Al, B = Bh+Bl (bf16 hi/lo). Shared fp32 accumulators across 3 passes:
// AhBh + AhBl + AlBh.
// Tile: BM=BN=128, BK=64 (128B rows, SW128), 2-stage cp.async pipeline.
// 8 warps (2x4), warp tile 64x32 = 4x4 m16n8k16 tiles.
// Requires M,N % 128 == 0, K % 64 == 0.
// ---------------------------------------------------------------------------
#define GBK 64
#define SB  65536            // per stage: Ah 16K | Al 16K | Bh 16K | Bl 16K
#define OAH 0
#define OAL 16384
#define OBH 32768
#define OBL 49152
#define GEMM_SMEM (2 * SB)   // 131072

__global__ __launch_bounds__(256, 1)
void gemm_bf3(const __nv_bfloat16* __restrict__ Ah, const __nv_bfloat16* __restrict__ Al,
              const __nv_bfloat16* __restrict__ Bh, const __nv_bfloat16* __restrict__ Bl,
              const float* __restrict__ bias, float* __restrict__ C,
              int M, int N, int K) {
    extern __shared__ char sm[];
    const uint32_t smb = smem_u32(sm);
    const int tid  = threadIdx.x;
    const int lane = tid & 31;
    const int wid  = tid >> 5;
    const int wm   = wid >> 2;      // 0..1
    const int wn   = wid & 3;       // 0..3
    const int m0 = blockIdx.y * 128;
    const int n0 = blockIdx.x * 128;
    const int NC = K / GBK;

    const __nv_bfloat16* Agh = Ah + (size_t)m0 * K;
    const __nv_bfloat16* Agl = Al + (size_t)m0 * K;
    const __nv_bfloat16* Bgh = Bh + (size_t)n0 * K;
    const __nv_bfloat16* Bgl = Bl + (size_t)n0 * K;

    float acc[4][4][4];
    #pragma unroll
    for (int mt = 0; mt < 4; mt++)
        #pragma unroll
        for (int nt = 0; nt < 4; nt++)
            #pragma unroll
            for (int q = 0; q < 4; q++) acc[mt][nt][q] = 0.f;

    // Per-thread staging indices: 512 chunks of 16B per matrix tile... (128 rows x 8)
    // Each of 256 threads issues 4 chunks per matrix (16 cp.async per stage).
    auto load_stage = [&](int c, int s) {
        const uint32_t stg = smb + s * SB;
        const int k0 = c * GBK;
        #pragma unroll
        for (int i = 0; i < 4; i++) {
            int id = tid + i * 256;          // 0..1023
            int r = id >> 3, cc = id & 7;
            uint32_t so = SWZ128((uint32_t)(r * 128 + cc * 16));
            size_t go = (size_t)r * K + k0 + cc * 8;
            cp_async16(stg + OAH + so, Agh + go);
            cp_async16(stg + OAL + so, Agl + go);
            cp_async16(stg + OBH + so, Bgh + go);
            cp_async16(stg + OBL + so, Bgl + go);
        }
        asm volatile("cp.async.commit_group;" ::: "memory");
    };

    load_stage(0, 0);

    // ldmatrix lane-address components (within a 128x64 bf16 tile, 128B rows)
    const int arow = wm * 64 + (lane & 7) + ((lane >> 3) & 1) * 8;  // + mt*16
    const int akb  = (lane >> 4) * 16;                              // + ks*32
    const int brow = wn * 32 + (lane >> 4) * 8 + (lane & 7);        // + jj*16
    const int bkb  = ((lane >> 3) & 1) * 16;                        // + ks*32

    for (int c = 0; c < NC; c++) {
        const int s = c & 1;
        if (c + 1 < NC) {
            load_stage(c + 1, s ^ 1);
            asm volatile("cp.async.wait_group 1;" ::: "memory");
        } else {
            asm volatile("cp.async.wait_group 0;" ::: "memory");
        }
        __syncthreads();

        const uint32_t stg = smb + s * SB;

        #pragma unroll
        for (int ks = 0; ks < 4; ks++) {
            uint32_t ah[4][4], al[4][4], bh[4][2], bl[4][2];
            #pragma unroll
            for (int mt = 0; mt < 4; mt++) {
                uint32_t so = SWZ128((uint32_t)((arow + mt * 16) * 128 + ks * 32 + akb));
                ldsm4(ah[mt], stg + OAH + so);
                ldsm4(al[mt], stg + OAL + so);
            }
            #pragma unroll
            for (int jj = 0; jj < 2; jj++) {
                uint32_t so = SWZ128((uint32_t)((brow + jj * 16) * 128 + ks * 32 + bkb));
                uint32_t t[4];
                ldsm4(t, stg + OBH + so);
                bh[jj * 2][0] = t[0]; bh[jj * 2][1] = t[1];
                bh[jj * 2 + 1][0] = t[2]; bh[jj * 2 + 1][1] = t[3];
                ldsm4(t, stg + OBL + so);
                bl[jj * 2][0] = t[0]; bl[jj * 2][1] = t[1];
                bl[jj * 2 + 1][0] = t[2]; bl[jj * 2 + 1][1] = t[3];
            }
            #pragma unroll
            for (int mt = 0; mt < 4; mt++)
                #pragma unroll
                for (int nt = 0; nt < 4; nt++)
                    mma16816(acc[mt][nt], ah[mt], bh[nt]);
            #pragma unroll
            for (int mt = 0; mt < 4; mt++)
                #pragma unroll
                for (int nt = 0; nt < 4; nt++)
                    mma16816(acc[mt][nt], ah[mt], bl[nt]);
            #pragma unroll
            for (int mt = 0; mt < 4; mt++)
                #pragma unroll
                for (int nt = 0; nt < 4; nt++)
                    mma16816(acc[mt][nt], al[mt], bh[nt]);
        }
        __syncthreads();
    }

    // Epilogue: bias add + store (d-frag rows lane>>2 / +8, cols (lane&3)*2, +1)
    const int rb = m0 + wm * 64 + (lane >> 2);
    const int cb = n0 + wn * 32 + (lane & 3) * 2;
    #pragma unroll
    for (int mt = 0; mt < 4; mt++) {
        #pragma unroll
        for (int nt = 0; nt < 4; nt++) {
            int r0 = rb + mt * 16;
            int cc = cb + nt * 8;
            float2 b = *(const float2*)(bias + cc);
            float2 v0, v1;
            v0.x = acc[mt][nt][0] + b.x; v0.y = acc[mt][nt][1] + b.y;
            v1.x = acc[mt][nt][2] + b.x; v1.y = acc[mt][nt][3] + b.y;
            *(float2*)(C + (size_t)r0 * N + cc)       = v0;
            *(float2*)(C + (size_t)(r0 + 8) * N + cc) = v1;
        }
    }
}

// ---------------------------------------------------------------------------
// Partial RoPE (reference has NO sign flip)
// ---------------------------------------------------------------------------
__global__ void rope_kernel(float* __restrict__ qkv,
                            const float* __restrict__ cosT,
                            const float* __restrict__ sinT) {
    int idx = blockIdx.x * blockDim.x + threadIdx.x;
    if (idx >= SEQ * NHEAD * 16) return;
    int d = idx & 15;
    int h = (idx >> 4) & 31;
    int t = idx >> 9;

    float c  = cosT[t * RD + d];
    float s  = sinT[t * RD + d];
    float c2 = cosT[t * RD + d + 16];
    float s2 = sinT[t * RD + d + 16];

    float* q = qkv + (size_t)t * OPSIZE + h * HDIM;
    float x0 = q[d], x1 = q[d + 16];
    q[d]      = x0 * c  + x1 * s;
    q[d + 16] = x1 * c2 + x0 * s2;

    float* k = q + NEMBD;
    x0 = k[d]; x1 = k[d + 16];
    k[d]      = x0 * c  + x1 * s;
    k[d + 16] = x1 * c2 + x0 * s2;
}

// ---------------------------------------------------------------------------
// Flash-attention (fp32, causal) — unchanged
// ---------------------------------------------------------------------------
__global__ __launch_bounds__(256, 2)
void flash_attn(const float* __restrict__ qkv, float* __restrict__ out) {
    extern __shared__ float smf[];
    float* Qs = smf;                 // [80][68]
    float* Ks = smf + 5440;          // [80][68]
    float* Ss = smf + 10880;         // [64][68]
    float* Vs = smf + 15232;         // [64][80]

    const int h  = blockIdx.y;
    const int qb = blockIdx.x;
    const int q0 = qb * 64;
    const int tid = threadIdx.x;
    const int tx = tid & 15;
    const int ty = tid >> 4;
    const int ty4 = ty * 4, tx4 = tx * 4, tx5 = tx * 5;

    const float scale = 0.11180339887498948f;
    const float* Qg = qkv + h * HDIM;
    const float* Kg = qkv + NEMBD + h * HDIM;
    const float* Vg = qkv + 2 * NEMBD + h * HDIM;

    for (int i = tid; i < 64 * 80; i += 256) {
        int r = i / 80, d = i % 80;
        Qs[d * 68 + r] = Qg[(size_t)(q0 + r) * OPSIZE + d] * scale;
    }

    float m_i[4], l_i[4], acc[4][5];
    #pragma unroll
    for (int i = 0; i < 4; i++) {
        m_i[i] = -1e30f; l_i[i] = 0.f;
        #pragma unroll
        for (int c = 0; c < 5; c++) acc[i][c] = 0.f;
    }

    const int ntiles = qb + 1;
    for (int tile = 0; tile < ntiles; tile++) {
        const int j0 = tile * 64;
        __syncthreads();
        for (int i = tid; i < 64 * 80; i += 256) {
            int r = i / 80, d = i % 80;
            Ks[d * 68 + r] = Kg[(size_t)(j0 + r) * OPSIZE + d];
            Vs[i]          = Vg[(size_t)(j0 + r) * OPSIZE + d];
        }
        __syncthreads();

        float s[4][4];
        #pragma unroll
        for (int i = 0; i < 4; i++)
            #pragma unroll
            for (int j = 0; j < 4; j++) s[i][j] = 0.f;

        #pragma unroll 8
        for (int d = 0; d < 80; d++) {
            float4 qv = *(const float4*)&Qs[d * 68 + ty4];
            float4 kv = *(const float4*)&Ks[d * 68 + tx4];
            float qa[4] = {qv.x, qv.y, qv.z, qv.w};
            float ka[4] = {kv.x, kv.y, kv.z, kv.w};
            #pragma unroll
            for (int i = 0; i < 4; i++)
                #pragma unroll
                for (int j = 0; j < 4; j++)
                    s[i][j] = fmaf(qa[i], ka[j], s[i][j]);
        }

        if (j0 == q0) {
            #pragma unroll
            for (int i = 0; i < 4; i++)
                #pragma unroll
                for (int j = 0; j < 4; j++)
                    if (tx4 + j > ty4 + i) s[i][j] = -1e30f;
        }

        #pragma unroll
        for (int i = 0; i < 4; i++) {
            float mx = fmaxf(fmaxf(s[i][0], s[i][1]), fmaxf(s[i][2], s[i][3]));
            #pragma unroll
            for (int off = 8; off >= 1; off >>= 1)
                mx = fmaxf(mx, __shfl_xor_sync(0xffffffffu, mx, off));
            float m_new = fmaxf(m_i[i], mx);
            float alpha = __expf(m_i[i] - m_new);
            float lp = 0.f;
            #pragma unroll
            for (int j = 0; j < 4; j++) {
                float p = __expf(s[i][j] - m_new);
                lp += p;
                Ss[(ty4 + i) * 68 + tx4 + j] = p;
            }
            #pragma unroll
            for (int off = 8; off >= 1; off >>= 1)
                lp += __shfl_xor_sync(0xffffffffu, lp, off);
            l_i[i] = l_i[i] * alpha + lp;
            m_i[i] = m_new;
            #pragma unroll
            for (int c = 0; c < 5; c++) acc[i][c] *= alpha;
        }
        __syncthreads();

        #pragma unroll 4
        for (int j = 0; j < 64; j++) {
            float p[4];
            #pragma unroll
            for (int i = 0; i < 4; i++) p[i] = Ss[(ty4 + i) * 68 + j];
            #pragma unroll
            for (int c = 0; c < 5; c++) {
                float v = Vs[j * 80 + tx5 + c];
                #pragma unroll
                for (int i = 0; i < 4; i++)
                    acc[i][c] = fmaf(p[i], v, acc[i][c]);
            }
        }
    }

    #pragma unroll
    for (int i = 0; i < 4; i++) {
        float inv = 1.f / l_i[i];
        int r = q0 + ty4 + i;
        float* orow = out + (size_t)r * NEMBD + h * HDIM + tx5;
        #pragma unroll
        for (int c = 0; c < 5; c++) orow[c] = acc[i][c] * inv;
    }
}

// ---------------------------------------------------------------------------
// Launch
// ---------------------------------------------------------------------------
extern "C" void kernel_launch(void* const* d_in, const int* in_sizes, int n_in,
                              void* d_out, int out_size) {
    const float* hidden = (const float*)d_in[0];
    const float* Wqkv_w = (const float*)d_in[1];
    const float* Wqkv_b = (const float*)d_in[2];
    const float* out_w  = (const float*)d_in[3];
    const float* out_b  = (const float*)d_in[4];
    const float* cosT   = (const float*)d_in[5];
    const float* sinT   = (const float*)d_in[6];
    float* out = (float*)d_out;

    float *qkv, *att;
    cudaGetSymbolAddress((void**)&qkv, g_qkv);
    cudaGetSymbolAddress((void**)&att, g_att);
    __nv_bfloat16 *Hh, *Hl, *Wh, *Wl, *Ch, *Cl, *Oh, *Ol;
    cudaGetSymbolAddress((void**)&Hh, g_Hh); cudaGetSymbolAddress((void**)&Hl, g_Hl);
    cudaGetSymbolAddress((void**)&Wh, g_Wh); cudaGetSymbolAddress((void**)&Wl, g_Wl);
    cudaGetSymbolAddress((void**)&Ch, g_Ch); cudaGetSymbolAddress((void**)&Cl, g_Cl);
    cudaGetSymbolAddress((void**)&Oh, g_Oh); cudaGetSymbolAddress((void**)&Ol, g_Ol);

    cudaFuncSetAttribute(gemm_bf3, cudaFuncAttributeMaxDynamicSharedMemorySize, GEMM_SMEM);
    cudaFuncSetAttribute(flash_attn, cudaFuncAttributeMaxDynamicSharedMemorySize, 81408);

    // Split inputs to bf16 hi/lo
    {
        int n4 = SEQ * NEMBD / 4;
        cvt_split<<<(n4 + 255) / 256, 256>>>(hidden, Hh, Hl, n4);
        n4 = OPSIZE * NEMBD / 4;
        cvt_split<<<(n4 + 255) / 256, 256>>>(Wqkv_w, Wh, Wl, n4);
    }

    // 1) QKV = H @ Wqkv^T + b  (HMMA bf16x3)
    {
        dim3 grid(OPSIZE / 128, SEQ / 128);
        gemm_bf3<<<grid, 256, GEMM_SMEM>>>(Hh, Hl, Wh, Wl, Wqkv_b, qkv,
                                           SEQ, OPSIZE, NEMBD);
    }

    // 2) Partial RoPE on Q and K
    {
        int total = SEQ * NHEAD * 16;
        rope_kernel<<<(total + 255) / 256, 256>>>(qkv, cosT, sinT);
    }

    // 3) Causal flash attention
    {
        dim3 grid(SEQ / 64, NHEAD);
        flash_attn<<<grid, 256, 81408>>>(qkv, att);
    }

    // 4) out = att @ out_w^T + out_b  (HMMA bf16x3)
    {
        int n4 = SEQ * NEMBD / 4;
        cvt_split<<<(n4 + 255) / 256, 256>>>(att, Ch, Cl, n4);
        n4 = NEMBD * NEMBD / 4;
        cvt_split<<<(n4 + 255) / 256, 256>>>(out_w, Oh, Ol, n4);
        dim3 grid(NEMBD / 128, SEQ / 128);
        gemm_bf3<<<grid, 256, GEMM_SMEM>>>(Ch, Cl, Oh, Ol, out_b, out,
                                           SEQ, NEMBD, NEMBD);
    }
}

// round 10
// speedup vs baseline: 2.4103x; 1.1473x over previous
#include <cuda_runtime.h>
#include <cuda_fp16.h>
#include <cuda_bf16.h>
#include <math.h>
#include <stdint.h>

// Problem constants
#define SEQ     2048
#define NEMBD   2560
#define NHEAD   32
#define HDIM    80
#define RD      32
#define OPSIZE  7680   // 3 * NEMBD

// ---------------------------------------------------------------------------
// Static device scratch (allocation-free per harness rules)
// ---------------------------------------------------------------------------
__device__ float g_qkv[SEQ * OPSIZE];
__device__ float g_att[SEQ * NEMBD];

__device__ __half g_Ha[SEQ * NEMBD];                          // hidden, fp16 trunc
__device__ __half g_Wh[OPSIZE * NEMBD], g_Wl[OPSIZE * NEMBD]; // Wqkv hi/lo
__device__ __half g_Ca[SEQ * NEMBD];                          // att, fp16 trunc
__device__ __half g_Oh[NEMBD * NEMBD], g_Ol[NEMBD * NEMBD];   // out_w hi/lo

// ---------------------------------------------------------------------------
// Helpers (base-target instructions only: cp.async / ldmatrix / mma.sync)
// ---------------------------------------------------------------------------
__device__ __forceinline__ uint32_t smem_u32(const void* p) {
    uint32_t a;
    asm("{ .reg .u64 t; cvta.to.shared.u64 t, %1; cvt.u32.u64 %0, t; }"
        : "=r"(a) : "l"(p));
    return a;
}
#define SWZ128(o) ((o) ^ (((o) >> 3) & 0x70))

__device__ __forceinline__ void cp_async16(uint32_t s, const void* g) {
    asm volatile("cp.async.cg.shared.global [%0], [%1], 16;\n" :: "r"(s), "l"(g));
}

__device__ __forceinline__ void ldsm4(uint32_t* r, uint32_t a) {
    asm volatile("ldmatrix.sync.aligned.m8n8.x4.shared.b16 {%0,%1,%2,%3}, [%4];"
        : "=r"(r[0]), "=r"(r[1]), "=r"(r[2]), "=r"(r[3]) : "r"(a));
}

__device__ __forceinline__ void mma16816h(float* d, const uint32_t* a, const uint32_t* b) {
    asm volatile(
        "mma.sync.aligned.m16n8k16.row.col.f32.f16.f16.f32 "
        "{%0,%1,%2,%3}, {%4,%5,%6,%7}, {%8,%9}, {%0,%1,%2,%3};"
        : "+f"(d[0]), "+f"(d[1]), "+f"(d[2]), "+f"(d[3])
        : "r"(a[0]), "r"(a[1]), "r"(a[2]), "r"(a[3]), "r"(b[0]), "r"(b[1]));
}

// ---------------------------------------------------------------------------
// fp32 -> fp16 truncate (activations)
// ---------------------------------------------------------------------------
__global__ void cvt_trunc(const float* __restrict__ x,
                          __half* __restrict__ h, int n4) {
    int i = blockIdx.x * blockDim.x + threadIdx.x;
    if (i >= n4) return;
    float4 v = ((const float4*)x)[i];
    __half2* hp = (__half2*)(h + i * 4);
    hp[0] = __floats2half2_rn(v.x, v.y);
    hp[1] = __floats2half2_rn(v.z, v.w);
}

// ---------------------------------------------------------------------------
// fp32 -> fp16 hi/lo split (weights)
// ---------------------------------------------------------------------------
__global__ void cvt_split16(const float* __restrict__ x,
                            __half* __restrict__ hi,
                            __half* __restrict__ lo, int n4) {
    int i = blockIdx.x * blockDim.x + threadIdx.x;
    if (i >= n4) return;
    float4 v = ((const float4*)x)[i];
    __half h0 = __float2half_rn(v.x);
    __half h1 = __float2half_rn(v.y);
    __half h2 = __float2half_rn(v.z);
    __half h3 = __float2half_rn(v.w);
    __half l0 = __float2half_rn(v.x - __half2float(h0));
    __half l1 = __float2half_rn(v.y - __half2float(h1));
    __half l2 = __float2half_rn(v.z - __half2float(h2));
    __half l3 = __float2half_rn(v.w - __half2float(h3));
    __half2* hp = (__half2*)(hi + i * 4);
    __half2* lp = (__half2*)(lo + i * 4);
    hp[0] = __half2(h0, h1); hp[1] = __half2(h2, h3);
    lp[0] = __half2(l0, l1); lp[1] = __half2(l2, l3);
}

// ---------------------------------------------------------------------------
// HMMA fp16 2-product GEMM:  C[m,n] = sum_k A[m,k]*B[n,k] + bias[n]
// A fp16-truncated (Ah), B split hi/lo (Bh+Bl): C = Ah*Bh + Ah*Bl = Ah*B.
// Tile: BM=BN=128, BK=64 (128B rows, SW128), 2-stage cp.async pipeline.
// 8 warps (2x4), warp tile 64x32 = 4x4 m16n8k16 tiles.
// Requires M,N % 128 == 0, K % 64 == 0.
// ---------------------------------------------------------------------------
#define GBK 64
#define SB  49152            // per stage: Ah 16K | Bh 16K | Bl 16K
#define OAH 0
#define OBH 16384
#define OBL 32768
#define GEMM_SMEM (2 * SB)   // 98304

__global__ __launch_bounds__(256, 1)
void gemm_fp16(const __half* __restrict__ Ah,
               const __half* __restrict__ Bh, const __half* __restrict__ Bl,
               const float* __restrict__ bias, float* __restrict__ C,
               int M, int N, int K) {
    extern __shared__ char sm[];
    const uint32_t smb = smem_u32(sm);
    const int tid  = threadIdx.x;
    const int lane = tid & 31;
    const int wid  = tid >> 5;
    const int wm   = wid >> 2;      // 0..1
    const int wn   = wid & 3;       // 0..3
    const int m0 = blockIdx.y * 128;
    const int n0 = blockIdx.x * 128;
    const int NC = K / GBK;

    const __half* Agh = Ah + (size_t)m0 * K;
    const __half* Bgh = Bh + (size_t)n0 * K;
    const __half* Bgl = Bl + (size_t)n0 * K;

    float acc[4][4][4];
    #pragma unroll
    for (int mt = 0; mt < 4; mt++)
        #pragma unroll
        for (int nt = 0; nt < 4; nt++)
            #pragma unroll
            for (int q = 0; q < 4; q++) acc[mt][nt][q] = 0.f;

    // 1024 x 16B chunks per 128x64 fp16 tile; 3 tiles -> 12 cp.async/thread
    auto load_stage = [&](int c, int s) {
        const uint32_t stg = smb + s * SB;
        const int k0 = c * GBK;
        #pragma unroll
        for (int i = 0; i < 4; i++) {
            int id = tid + i * 256;          // 0..1023
            int r = id >> 3, cc = id & 7;
            uint32_t so = SWZ128((uint32_t)(r * 128 + cc * 16));
            size_t go = (size_t)r * K + k0 + cc * 8;
            cp_async16(stg + OAH + so, Agh + go);
            cp_async16(stg + OBH + so, Bgh + go);
            cp_async16(stg + OBL + so, Bgl + go);
        }
        asm volatile("cp.async.commit_group;" ::: "memory");
    };

    load_stage(0, 0);

    // ldmatrix lane-address components (within a 128x64 fp16 tile, 128B rows)
    const int arow = wm * 64 + (lane & 7) + ((lane >> 3) & 1) * 8;  // + mt*16
    const int akb  = (lane >> 4) * 16;                              // + ks*32
    const int brow = wn * 32 + (lane >> 4) * 8 + (lane & 7);        // + jj*16
    const int bkb  = ((lane >> 3) & 1) * 16;                        // + ks*32

    for (int c = 0; c < NC; c++) {
        const int s = c & 1;
        if (c + 1 < NC) {
            load_stage(c + 1, s ^ 1);
            asm volatile("cp.async.wait_group 1;" ::: "memory");
        } else {
            asm volatile("cp.async.wait_group 0;" ::: "memory");
        }
        __syncthreads();

        const uint32_t stg = smb + s * SB;

        #pragma unroll
        for (int ks = 0; ks < 4; ks++) {
            uint32_t ah[4][4], bh[4][2], bl[4][2];
            #pragma unroll
            for (int mt = 0; mt < 4; mt++) {
                uint32_t so = SWZ128((uint32_t)((arow + mt * 16) * 128 + ks * 32 + akb));
                ldsm4(ah[mt], stg + OAH + so);
            }
            #pragma unroll
            for (int jj = 0; jj < 2; jj++) {
                uint32_t so = SWZ128((uint32_t)((brow + jj * 16) * 128 + ks * 32 + bkb));
                uint32_t t[4];
                ldsm4(t, stg + OBH + so);
                bh[jj * 2][0] = t[0]; bh[jj * 2][1] = t[1];
                bh[jj * 2 + 1][0] = t[2]; bh[jj * 2 + 1][1] = t[3];
                ldsm4(t, stg + OBL + so);
                bl[jj * 2][0] = t[0]; bl[jj * 2][1] = t[1];
                bl[jj * 2 + 1][0] = t[2]; bl[jj * 2 + 1][1] = t[3];
            }
            #pragma unroll
            for (int mt = 0; mt < 4; mt++)
                #pragma unroll
                for (int nt = 0; nt < 4; nt++)
                    mma16816h(acc[mt][nt], ah[mt], bh[nt]);
            #pragma unroll
            for (int mt = 0; mt < 4; mt++)
                #pragma unroll
                for (int nt = 0; nt < 4; nt++)
                    mma16816h(acc[mt][nt], ah[mt], bl[nt]);
        }
        __syncthreads();
    }

    // Epilogue: bias add + store
    const int rb = m0 + wm * 64 + (lane >> 2);
    const int cb = n0 + wn * 32 + (lane & 3) * 2;
    #pragma unroll
    for (int mt = 0; mt < 4; mt++) {
        #pragma unroll
        for (int nt = 0; nt < 4; nt++) {
            int r0 = rb + mt * 16;
            int cc = cb + nt * 8;
            float2 b = *(const float2*)(bias + cc);
            float2 v0, v1;
            v0.x = acc[mt][nt][0] + b.x; v0.y = acc[mt][nt][1] + b.y;
            v1.x = acc[mt][nt][2] + b.x; v1.y = acc[mt][nt][3] + b.y;
            *(float2*)(C + (size_t)r0 * N + cc)       = v0;
            *(float2*)(C + (size_t)(r0 + 8) * N + cc) = v1;
        }
    }
}

// ---------------------------------------------------------------------------
// Partial RoPE (reference has NO sign flip)
// ---------------------------------------------------------------------------
__global__ void rope_kernel(float* __restrict__ qkv,
                            const float* __restrict__ cosT,
                            const float* __restrict__ sinT) {
    int idx = blockIdx.x * blockDim.x + threadIdx.x;
    if (idx >= SEQ * NHEAD * 16) return;
    int d = idx & 15;
    int h = (idx >> 4) & 31;
    int t = idx >> 9;

    float c  = cosT[t * RD + d];
    float s  = sinT[t * RD + d];
    float c2 = cosT[t * RD + d + 16];
    float s2 = sinT[t * RD + d + 16];

    float* q = qkv + (size_t)t * OPSIZE + h * HDIM;
    float x0 = q[d], x1 = q[d + 16];
    q[d]      = x0 * c  + x1 * s;
    q[d + 16] = x1 * c2 + x0 * s2;

    float* k = q + NEMBD;
    x0 = k[d]; x1 = k[d + 16];
    k[d]      = x0 * c  + x1 * s;
    k[d + 16] = x1 * c2 + x0 * s2;
}

// ---------------------------------------------------------------------------
// Flash-attention (fp32, causal) — unchanged
// ---------------------------------------------------------------------------
__global__ __launch_bounds__(256, 2)
void flash_attn(const float* __restrict__ qkv, float* __restrict__ out) {
    extern __shared__ float smf[];
    float* Qs = smf;                 // [80][68]
    float* Ks = smf + 5440;          // [80][68]
    float* Ss = smf + 10880;         // [64][68]
    float* Vs = smf + 15232;         // [64][80]

    const int h  = blockIdx.y;
    const int qb = blockIdx.x;
    const int q0 = qb * 64;
    const int tid = threadIdx.x;
    const int tx = tid & 15;
    const int ty = tid >> 4;
    const int ty4 = ty * 4, tx4 = tx * 4, tx5 = tx * 5;

    const float scale = 0.11180339887498948f;
    const float* Qg = qkv + h * HDIM;
    const float* Kg = qkv + NEMBD + h * HDIM;
    const float* Vg = qkv + 2 * NEMBD + h * HDIM;

    for (int i = tid; i < 64 * 80; i += 256) {
        int r = i / 80, d = i % 80;
        Qs[d * 68 + r] = Qg[(size_t)(q0 + r) * OPSIZE + d] * scale;
    }

    float m_i[4], l_i[4], acc[4][5];
    #pragma unroll
    for (int i = 0; i < 4; i++) {
        m_i[i] = -1e30f; l_i[i] = 0.f;
        #pragma unroll
        for (int c = 0; c < 5; c++) acc[i][c] = 0.f;
    }

    const int ntiles = qb + 1;
    for (int tile = 0; tile < ntiles; tile++) {
        const int j0 = tile * 64;
        __syncthreads();
        for (int i = tid; i < 64 * 80; i += 256) {
            int r = i / 80, d = i % 80;
            Ks[d * 68 + r] = Kg[(size_t)(j0 + r) * OPSIZE + d];
            Vs[i]          = Vg[(size_t)(j0 + r) * OPSIZE + d];
        }
        __syncthreads();

        float s[4][4];
        #pragma unroll
        for (int i = 0; i < 4; i++)
            #pragma unroll
            for (int j = 0; j < 4; j++) s[i][j] = 0.f;

        #pragma unroll 8
        for (int d = 0; d < 80; d++) {
            float4 qv = *(const float4*)&Qs[d * 68 + ty4];
            float4 kv = *(const float4*)&Ks[d * 68 + tx4];
            float qa[4] = {qv.x, qv.y, qv.z, qv.w};
            float ka[4] = {kv.x, kv.y, kv.z, kv.w};
            #pragma unroll
            for (int i = 0; i < 4; i++)
                #pragma unroll
                for (int j = 0; j < 4; j++)
                    s[i][j] = fmaf(qa[i], ka[j], s[i][j]);
        }

        if (j0 == q0) {
            #pragma unroll
            for (int i = 0; i < 4; i++)
                #pragma unroll
                for (int j = 0; j < 4; j++)
                    if (tx4 + j > ty4 + i) s[i][j] = -1e30f;
        }

        #pragma unroll
        for (int i = 0; i < 4; i++) {
            float mx = fmaxf(fmaxf(s[i][0], s[i][1]), fmaxf(s[i][2], s[i][3]));
            #pragma unroll
            for (int off = 8; off >= 1; off >>= 1)
                mx = fmaxf(mx, __shfl_xor_sync(0xffffffffu, mx, off));
            float m_new = fmaxf(m_i[i], mx);
            float alpha = __expf(m_i[i] - m_new);
            float lp = 0.f;
            #pragma unroll
            for (int j = 0; j < 4; j++) {
                float p = __expf(s[i][j] - m_new);
                lp += p;
                Ss[(ty4 + i) * 68 + tx4 + j] = p;
            }
            #pragma unroll
            for (int off = 8; off >= 1; off >>= 1)
                lp += __shfl_xor_sync(0xffffffffu, lp, off);
            l_i[i] = l_i[i] * alpha + lp;
            m_i[i] = m_new;
            #pragma unroll
            for (int c = 0; c < 5; c++) acc[i][c] *= alpha;
        }
        __syncthreads();

        #pragma unroll 4
        for (int j = 0; j < 64; j++) {
            float p[4];
            #pragma unroll
            for (int i = 0; i < 4; i++) p[i] = Ss[(ty4 + i) * 68 + j];
            #pragma unroll
            for (int c = 0; c < 5; c++) {
                float v = Vs[j * 80 + tx5 + c];
                #pragma unroll
                for (int i = 0; i < 4; i++)
                    acc[i][c] = fmaf(p[i], v, acc[i][c]);
            }
        }
    }

    #pragma unroll
    for (int i = 0; i < 4; i++) {
        float inv = 1.f / l_i[i];
        int r = q0 + ty4 + i;
        float* orow = out + (size_t)r * NEMBD + h * HDIM + tx5;
        #pragma unroll
        for (int c = 0; c < 5; c++) orow[c] = acc[i][c] * inv;
    }
}

// ---------------------------------------------------------------------------
// Launch
// ---------------------------------------------------------------------------
extern "C" void kernel_launch(void* const* d_in, const int* in_sizes, int n_in,
                              void* d_out, int out_size) {
    const float* hidden = (const float*)d_in[0];
    const float* Wqkv_w = (const float*)d_in[1];
    const float* Wqkv_b = (const float*)d_in[2];
    const float* out_w  = (const float*)d_in[3];
    const float* out_b  = (const float*)d_in[4];
    const float* cosT   = (const float*)d_in[5];
    const float* sinT   = (const float*)d_in[6];
    float* out = (float*)d_out;

    float *qkv, *att;
    cudaGetSymbolAddress((void**)&qkv, g_qkv);
    cudaGetSymbolAddress((void**)&att, g_att);
    __half *Ha, *Wh, *Wl, *Ca, *Oh, *Ol;
    cudaGetSymbolAddress((void**)&Ha, g_Ha);
    cudaGetSymbolAddress((void**)&Wh, g_Wh); cudaGetSymbolAddress((void**)&Wl, g_Wl);
    cudaGetSymbolAddress((void**)&Ca, g_Ca);
    cudaGetSymbolAddress((void**)&Oh, g_Oh); cudaGetSymbolAddress((void**)&Ol, g_Ol);

    cudaFuncSetAttribute(gemm_fp16, cudaFuncAttributeMaxDynamicSharedMemorySize, GEMM_SMEM);
    cudaFuncSetAttribute(flash_attn, cudaFuncAttributeMaxDynamicSharedMemorySize, 81408);

    // Convert inputs
    {
        int n4 = SEQ * NEMBD / 4;
        cvt_trunc<<<(n4 + 255) / 256, 256>>>(hidden, Ha, n4);
        n4 = OPSIZE * NEMBD / 4;
        cvt_split16<<<(n4 + 255) / 256, 256>>>(Wqkv_w, Wh, Wl, n4);
    }

    // 1) QKV = H @ Wqkv^T + b  (HMMA fp16, 2 products)
    {
        dim3 grid(OPSIZE / 128, SEQ / 128);
        gemm_fp16<<<grid, 256, GEMM_SMEM>>>(Ha, Wh, Wl, Wqkv_b, qkv,
                                            SEQ, OPSIZE, NEMBD);
    }

    // 2) Partial RoPE on Q and K
    {
        int total = SEQ * NHEAD * 16;
        rope_kernel<<<(total + 255) / 256, 256>>>(qkv, cosT, sinT);
    }

    // 3) Causal flash attention
    {
        dim3 grid(SEQ / 64, NHEAD);
        flash_attn<<<grid, 256, 81408>>>(qkv, att);
    }

    // 4) out = att @ out_w^T + out_b  (HMMA fp16, 2 products)
    {
        int n4 = SEQ * NEMBD / 4;
        cvt_trunc<<<(n4 + 255) / 256, 256>>>(att, Ca, n4);
        n4 = NEMBD * NEMBD / 4;
        cvt_split16<<<(n4 + 255) / 256, 256>>>(out_w, Oh, Ol, n4);
        dim3 grid(NEMBD / 128, SEQ / 128);
        gemm_fp16<<<grid, 256, GEMM_SMEM>>>(Ca, Oh, Ol, out_b, out,
                                            SEQ, NEMBD, NEMBD);
    }
}

// round 11
// speedup vs baseline: 4.8712x; 2.0210x over previous
#include <cuda_runtime.h>
#include <cuda_fp16.h>
#include <cuda_bf16.h>
#include <math.h>
#include <stdint.h>

// Problem constants
#define SEQ     2048
#define NEMBD   2560
#define NHEAD   32
#define HDIM    80
#define RD      32
#define OPSIZE  7680   // 3 * NEMBD

// ---------------------------------------------------------------------------
// Static device scratch (allocation-free per harness rules)
// ---------------------------------------------------------------------------
__device__ float g_qkv[SEQ * OPSIZE];

__device__ __half g_Ha[SEQ * NEMBD];                          // hidden, fp16 trunc
__device__ __half g_Wh[OPSIZE * NEMBD], g_Wl[OPSIZE * NEMBD]; // Wqkv hi/lo
__device__ __half g_Ca[SEQ * NEMBD];                          // att out, fp16
__device__ __half g_Oh[NEMBD * NEMBD], g_Ol[NEMBD * NEMBD];   // out_w hi/lo

__device__ __half g_Qh[NHEAD * SEQ * HDIM];                   // head-major Q (scaled)
__device__ __half g_Kh[NHEAD * SEQ * HDIM];
__device__ __half g_Vh[NHEAD * SEQ * HDIM];

// ---------------------------------------------------------------------------
// Helpers (base-target instructions only: cp.async / ldmatrix / mma.sync)
// ---------------------------------------------------------------------------
__device__ __forceinline__ uint32_t smem_u32(const void* p) {
    uint32_t a;
    asm("{ .reg .u64 t; cvta.to.shared.u64 t, %1; cvt.u32.u64 %0, t; }"
        : "=r"(a) : "l"(p));
    return a;
}
#define SWZ128(o) ((o) ^ (((o) >> 3) & 0x70))
// Padded-atom tile offset: rows of 128 fp16 logical cols, atoms 8r x 64c
#define TOFF(r, c) ((((r) >> 3) * 2048) + ((((c) >> 6)) << 10) + \
                    SWZ128((((r) & 7) << 7) + (((c) & 63) << 1)))

__device__ __forceinline__ void cp_async16(uint32_t s, const void* g) {
    asm volatile("cp.async.cg.shared.global [%0], [%1], 16;\n" :: "r"(s), "l"(g));
}

__device__ __forceinline__ void ldsm4(uint32_t* r, uint32_t a) {
    asm volatile("ldmatrix.sync.aligned.m8n8.x4.shared.b16 {%0,%1,%2,%3}, [%4];"
        : "=r"(r[0]), "=r"(r[1]), "=r"(r[2]), "=r"(r[3]) : "r"(a));
}
__device__ __forceinline__ void ldsm4t(uint32_t* r, uint32_t a) {
    asm volatile("ldmatrix.sync.aligned.m8n8.x4.trans.shared.b16 {%0,%1,%2,%3}, [%4];"
        : "=r"(r[0]), "=r"(r[1]), "=r"(r[2]), "=r"(r[3]) : "r"(a));
}

__device__ __forceinline__ void mma16816h(float* d, const uint32_t* a, const uint32_t* b) {
    asm volatile(
        "mma.sync.aligned.m16n8k16.row.col.f32.f16.f16.f32 "
        "{%0,%1,%2,%3}, {%4,%5,%6,%7}, {%8,%9}, {%0,%1,%2,%3};"
        : "+f"(d[0]), "+f"(d[1]), "+f"(d[2]), "+f"(d[3])
        : "r"(a[0]), "r"(a[1]), "r"(a[2]), "r"(a[3]), "r"(b[0]), "r"(b[1]));
}

__device__ __forceinline__ uint32_t h2u(float a, float b) {
    __half2 h = __floats2half2_rn(a, b);
    return *(uint32_t*)&h;
}

// ---------------------------------------------------------------------------
// fp32 -> fp16 truncate (activations)
// ---------------------------------------------------------------------------
__global__ void cvt_trunc(const float* __restrict__ x,
                          __half* __restrict__ h, int n4) {
    int i = blockIdx.x * blockDim.x + threadIdx.x;
    if (i >= n4) return;
    float4 v = ((const float4*)x)[i];
    __half2* hp = (__half2*)(h + i * 4);
    hp[0] = __floats2half2_rn(v.x, v.y);
    hp[1] = __floats2half2_rn(v.z, v.w);
}

// ---------------------------------------------------------------------------
// fp32 -> fp16 hi/lo split (weights)
// ---------------------------------------------------------------------------
__global__ void cvt_split16(const float* __restrict__ x,
                            __half* __restrict__ hi,
                            __half* __restrict__ lo, int n4) {
    int i = blockIdx.x * blockDim.x + threadIdx.x;
    if (i >= n4) return;
    float4 v = ((const float4*)x)[i];
    __half h0 = __float2half_rn(v.x);
    __half h1 = __float2half_rn(v.y);
    __half h2 = __float2half_rn(v.z);
    __half h3 = __float2half_rn(v.w);
    __half l0 = __float2half_rn(v.x - __half2float(h0));
    __half l1 = __float2half_rn(v.y - __half2float(h1));
    __half l2 = __float2half_rn(v.z - __half2float(h2));
    __half l3 = __float2half_rn(v.w - __half2float(h3));
    __half2* hp = (__half2*)(hi + i * 4);
    __half2* lp = (__half2*)(lo + i * 4);
    hp[0] = __half2(h0, h1); hp[1] = __half2(h2, h3);
    lp[0] = __half2(l0, l1); lp[1] = __half2(l2, l3);
}

// ---------------------------------------------------------------------------
// HMMA fp16 2-product GEMM:  C[m,n] = sum_k A[m,k]*B[n,k] + bias[n]
// (unchanged from R10)
// ---------------------------------------------------------------------------
#define GBK 64
#define SB  49152            // per stage: Ah 16K | Bh 16K | Bl 16K
#define OAH 0
#define OBH 16384
#define OBL 32768
#define GEMM_SMEM (2 * SB)   // 98304

__global__ __launch_bounds__(256, 1)
void gemm_fp16(const __half* __restrict__ Ah,
               const __half* __restrict__ Bh, const __half* __restrict__ Bl,
               const float* __restrict__ bias, float* __restrict__ C,
               int M, int N, int K) {
    extern __shared__ char sm[];
    const uint32_t smb = smem_u32(sm);
    const int tid  = threadIdx.x;
    const int lane = tid & 31;
    const int wid  = tid >> 5;
    const int wm   = wid >> 2;
    const int wn   = wid & 3;
    const int m0 = blockIdx.y * 128;
    const int n0 = blockIdx.x * 128;
    const int NC = K / GBK;

    const __half* Agh = Ah + (size_t)m0 * K;
    const __half* Bgh = Bh + (size_t)n0 * K;
    const __half* Bgl = Bl + (size_t)n0 * K;

    float acc[4][4][4];
    #pragma unroll
    for (int mt = 0; mt < 4; mt++)
        #pragma unroll
        for (int nt = 0; nt < 4; nt++)
            #pragma unroll
            for (int q = 0; q < 4; q++) acc[mt][nt][q] = 0.f;

    auto load_stage = [&](int c, int s) {
        const uint32_t stg = smb + s * SB;
        const int k0 = c * GBK;
        #pragma unroll
        for (int i = 0; i < 4; i++) {
            int id = tid + i * 256;
            int r = id >> 3, cc = id & 7;
            uint32_t so = SWZ128((uint32_t)(r * 128 + cc * 16));
            size_t go = (size_t)r * K + k0 + cc * 8;
            cp_async16(stg + OAH + so, Agh + go);
            cp_async16(stg + OBH + so, Bgh + go);
            cp_async16(stg + OBL + so, Bgl + go);
        }
        asm volatile("cp.async.commit_group;" ::: "memory");
    };

    load_stage(0, 0);

    const int arow = wm * 64 + (lane & 7) + ((lane >> 3) & 1) * 8;
    const int akb  = (lane >> 4) * 16;
    const int brow = wn * 32 + (lane >> 4) * 8 + (lane & 7);
    const int bkb  = ((lane >> 3) & 1) * 16;

    for (int c = 0; c < NC; c++) {
        const int s = c & 1;
        if (c + 1 < NC) {
            load_stage(c + 1, s ^ 1);
            asm volatile("cp.async.wait_group 1;" ::: "memory");
        } else {
            asm volatile("cp.async.wait_group 0;" ::: "memory");
        }
        __syncthreads();

        const uint32_t stg = smb + s * SB;

        #pragma unroll
        for (int ks = 0; ks < 4; ks++) {
            uint32_t ah[4][4], bh[4][2], bl[4][2];
            #pragma unroll
            for (int mt = 0; mt < 4; mt++) {
                uint32_t so = SWZ128((uint32_t)((arow + mt * 16) * 128 + ks * 32 + akb));
                ldsm4(ah[mt], stg + OAH + so);
            }
            #pragma unroll
            for (int jj = 0; jj < 2; jj++) {
                uint32_t so = SWZ128((uint32_t)((brow + jj * 16) * 128 + ks * 32 + bkb));
                uint32_t t[4];
                ldsm4(t, stg + OBH + so);
                bh[jj * 2][0] = t[0]; bh[jj * 2][1] = t[1];
                bh[jj * 2 + 1][0] = t[2]; bh[jj * 2 + 1][1] = t[3];
                ldsm4(t, stg + OBL + so);
                bl[jj * 2][0] = t[0]; bl[jj * 2][1] = t[1];
                bl[jj * 2 + 1][0] = t[2]; bl[jj * 2 + 1][1] = t[3];
            }
            #pragma unroll
            for (int mt = 0; mt < 4; mt++)
                #pragma unroll
                for (int nt = 0; nt < 4; nt++)
                    mma16816h(acc[mt][nt], ah[mt], bh[nt]);
            #pragma unroll
            for (int mt = 0; mt < 4; mt++)
                #pragma unroll
                for (int nt = 0; nt < 4; nt++)
                    mma16816h(acc[mt][nt], ah[mt], bl[nt]);
        }
        __syncthreads();
    }

    const int rb = m0 + wm * 64 + (lane >> 2);
    const int cb = n0 + wn * 32 + (lane & 3) * 2;
    #pragma unroll
    for (int mt = 0; mt < 4; mt++) {
        #pragma unroll
        for (int nt = 0; nt < 4; nt++) {
            int r0 = rb + mt * 16;
            int cc = cb + nt * 8;
            float2 b = *(const float2*)(bias + cc);
            float2 v0, v1;
            v0.x = acc[mt][nt][0] + b.x; v0.y = acc[mt][nt][1] + b.y;
            v1.x = acc[mt][nt][2] + b.x; v1.y = acc[mt][nt][3] + b.y;
            *(float2*)(C + (size_t)r0 * N + cc)       = v0;
            *(float2*)(C + (size_t)(r0 + 8) * N + cc) = v1;
        }
    }
}

// ---------------------------------------------------------------------------
// Fused RoPE (no sign flip) + fp16 pack to head-major [NHEAD][SEQ][80].
// Q pre-scaled by 1/sqrt(80).
// ---------------------------------------------------------------------------
__global__ void rope_pack(const float* __restrict__ qkv,
                          const float* __restrict__ cosT,
                          const float* __restrict__ sinT,
                          __half* __restrict__ Qh, __half* __restrict__ Kh,
                          __half* __restrict__ Vh) {
    int idx = blockIdx.x * blockDim.x + threadIdx.x;
    if (idx >= SEQ * NHEAD * HDIM) return;
    int d  = idx % HDIM;
    int th = idx / HDIM;
    int h  = th & 31;
    int t  = th >> 5;

    const float* base = qkv + (size_t)t * OPSIZE + h * HDIM;
    float q = base[d];
    float k = base[NEMBD + d];
    float v = base[2 * NEMBD + d];
    if (d < RD) {
        float c = cosT[t * RD + d];
        float s = sinT[t * RD + d];
        int dp = (d < 16) ? d + 16 : d - 16;
        q = q * c + base[dp] * s;
        k = k * c + base[NEMBD + dp] * s;
    }
    size_t o = ((size_t)h * SEQ + t) * HDIM + d;
    Qh[o] = __float2half(q * 0.11180339887498948f);
    Kh[o] = __float2half(k);
    Vh[o] = __float2half(v);
}

// ---------------------------------------------------------------------------
// HMMA fp16 flash attention (causal). Grid (qb, head), 128 threads (4 warps).
// BQ = BK = 64. Warp owns 16 q-rows. Smem: Q 16K + 2 stages x (K 16K + V 16K).
// Writes O directly as fp16 into att[t][h*80+d] (GEMM2 A operand).
// ---------------------------------------------------------------------------
#define FA_SMEM (16384 + 2 * 32768)   // 81920

__global__ __launch_bounds__(128, 2)
void flash_fp16(const __half* __restrict__ Qh, const __half* __restrict__ Kh,
                const __half* __restrict__ Vh, __half* __restrict__ att) {
    extern __shared__ char sm[];
    const uint32_t smb = smem_u32(sm);
    const int h = blockIdx.y;
    const int qb = blockIdx.x;
    const int q0 = qb * 64;
    const int tid = threadIdx.x;
    const int lane = tid & 31;
    const int wid = tid >> 5;

    const __half* Qg = Qh + ((size_t)h * SEQ + q0) * HDIM;
    const __half* Kg = Kh + (size_t)h * SEQ * HDIM;
    const __half* Vg = Vh + (size_t)h * SEQ * HDIM;

    const uint32_t SQ = smb;

    // Load Q tile (64 rows x 80 cols, 10 x 16B chunks per row)
    #pragma unroll
    for (int i = 0; i < 5; i++) {
        int id = tid + i * 128;
        int r = id / 10, c = id - r * 10;
        cp_async16(SQ + TOFF(r, c * 8), Qg + r * HDIM + c * 8);
    }
    asm volatile("cp.async.commit_group;" ::: "memory");

    auto load_kv = [&](int kb, int s) {
        const __half* kg = Kg + (size_t)kb * 64 * HDIM;
        const __half* vg = Vg + (size_t)kb * 64 * HDIM;
        uint32_t SK = smb + 16384 + s * 32768;
        uint32_t SV = SK + 16384;
        #pragma unroll
        for (int i = 0; i < 5; i++) {
            int id = tid + i * 128;
            int r = id / 10, c = id - r * 10;
            uint32_t o = TOFF(r, c * 8);
            cp_async16(SK + o, kg + r * HDIM + c * 8);
            cp_async16(SV + o, vg + r * HDIM + c * 8);
        }
        asm volatile("cp.async.commit_group;" ::: "memory");
    };

    load_kv(0, 0);
    asm volatile("cp.async.wait_group 0;" ::: "memory");
    __syncthreads();

    // Hoisted Q fragments: 5 k-chunks of 16
    uint32_t qf[5][4];
    {
        int row = wid * 16 + (lane & 7) + ((lane >> 3) & 1) * 8;
        #pragma unroll
        for (int ks = 0; ks < 5; ks++) {
            int col = ks * 16 + (lane >> 4) * 8;
            ldsm4(qf[ks], SQ + TOFF(row, col));
        }
    }

    float m0 = -1e30f, m1 = -1e30f, l0 = 0.f, l1 = 0.f;
    float oa[10][4];
    #pragma unroll
    for (int dt = 0; dt < 10; dt++)
        #pragma unroll
        for (int q = 0; q < 4; q++) oa[dt][q] = 0.f;

    const int krow = (lane >> 4) * 8 + (lane & 7);           // B-operand rows
    const int kcol = ((lane >> 3) & 1) * 8;                  // B-operand k off
    const int vrow = (lane & 7) + ((lane >> 3) & 1) * 8;     // V trans rows
    const int vcol = (lane >> 4) * 8;                        // V trans col off

    for (int kb = 0; kb <= qb; kb++) {
        const int s = kb & 1;
        if (kb < qb) {
            load_kv(kb + 1, s ^ 1);
            asm volatile("cp.async.wait_group 1;" ::: "memory");
        } else {
            asm volatile("cp.async.wait_group 0;" ::: "memory");
        }
        __syncthreads();
        const uint32_t SK = smb + 16384 + s * 32768;
        const uint32_t SV = SK + 16384;

        // S = Q K^T : 8 n-tiles x fp32 acc
        float sa[8][4];
        #pragma unroll
        for (int nt = 0; nt < 8; nt++)
            #pragma unroll
            for (int q = 0; q < 4; q++) sa[nt][q] = 0.f;

        #pragma unroll
        for (int ks = 0; ks < 5; ks++) {
            int col = ks * 16 + kcol;
            #pragma unroll
            for (int np = 0; np < 4; np++) {
                uint32_t t[4];
                ldsm4(t, SK + TOFF(np * 16 + krow, col));
                uint32_t b0[2] = { t[0], t[1] };
                uint32_t b1[2] = { t[2], t[3] };
                mma16816h(sa[2 * np],     qf[ks], b0);
                mma16816h(sa[2 * np + 1], qf[ks], b1);
            }
        }

        // Causal mask on the diagonal tile
        if (kb == qb) {
            int i0 = wid * 16 + (lane >> 2);
            int i1 = i0 + 8;
            #pragma unroll
            for (int nt = 0; nt < 8; nt++) {
                int j = nt * 8 + (lane & 3) * 2;
                if (j     > i0) sa[nt][0] = -1e30f;
                if (j + 1 > i0) sa[nt][1] = -1e30f;
                if (j     > i1) sa[nt][2] = -1e30f;
                if (j + 1 > i1) sa[nt][3] = -1e30f;
            }
        }

        // Online softmax (rows r0 = lane>>2, r1 = r0+8; cols across lane&3)
        float mx0 = -1e30f, mx1 = -1e30f;
        #pragma unroll
        for (int nt = 0; nt < 8; nt++) {
            mx0 = fmaxf(mx0, fmaxf(sa[nt][0], sa[nt][1]));
            mx1 = fmaxf(mx1, fmaxf(sa[nt][2], sa[nt][3]));
        }
        mx0 = fmaxf(mx0, __shfl_xor_sync(0xffffffffu, mx0, 1));
        mx0 = fmaxf(mx0, __shfl_xor_sync(0xffffffffu, mx0, 2));
        mx1 = fmaxf(mx1, __shfl_xor_sync(0xffffffffu, mx1, 1));
        mx1 = fmaxf(mx1, __shfl_xor_sync(0xffffffffu, mx1, 2));
        float mn0 = fmaxf(m0, mx0), mn1 = fmaxf(m1, mx1);
        float a0 = __expf(m0 - mn0), a1 = __expf(m1 - mn1);
        m0 = mn0; m1 = mn1;

        float lp0 = 0.f, lp1 = 0.f;
        #pragma unroll
        for (int nt = 0; nt < 8; nt++) {
            sa[nt][0] = __expf(sa[nt][0] - mn0);
            sa[nt][1] = __expf(sa[nt][1] - mn0);
            sa[nt][2] = __expf(sa[nt][2] - mn1);
            sa[nt][3] = __expf(sa[nt][3] - mn1);
            lp0 += sa[nt][0] + sa[nt][1];
            lp1 += sa[nt][2] + sa[nt][3];
        }
        lp0 += __shfl_xor_sync(0xffffffffu, lp0, 1);
        lp0 += __shfl_xor_sync(0xffffffffu, lp0, 2);
        lp1 += __shfl_xor_sync(0xffffffffu, lp1, 1);
        lp1 += __shfl_xor_sync(0xffffffffu, lp1, 2);
        l0 = l0 * a0 + lp0;
        l1 = l1 * a1 + lp1;

        #pragma unroll
        for (int dt = 0; dt < 10; dt++) {
            oa[dt][0] *= a0; oa[dt][1] *= a0;
            oa[dt][2] *= a1; oa[dt][3] *= a1;
        }

        // Pack P (C-fragment -> A-fragment identity)
        uint32_t pf[4][4];
        #pragma unroll
        for (int kt = 0; kt < 4; kt++) {
            pf[kt][0] = h2u(sa[2 * kt][0],     sa[2 * kt][1]);
            pf[kt][1] = h2u(sa[2 * kt][2],     sa[2 * kt][3]);
            pf[kt][2] = h2u(sa[2 * kt + 1][0], sa[2 * kt + 1][1]);
            pf[kt][3] = h2u(sa[2 * kt + 1][2], sa[2 * kt + 1][3]);
        }

        // O += P V  (V via ldmatrix.trans)
        #pragma unroll
        for (int kt = 0; kt < 4; kt++) {
            #pragma unroll
            for (int dp = 0; dp < 5; dp++) {
                uint32_t t[4];
                ldsm4t(t, SV + TOFF(kt * 16 + vrow, dp * 16 + vcol));
                uint32_t b0[2] = { t[0], t[1] };
                uint32_t b1[2] = { t[2], t[3] };
                mma16816h(oa[2 * dp],     pf[kt], b0);
                mma16816h(oa[2 * dp + 1], pf[kt], b1);
            }
        }
        __syncthreads();
    }

    // Normalize + write fp16 output att[t][h*80+d]
    float inv0 = 1.f / l0, inv1 = 1.f / l1;
    int r0 = q0 + wid * 16 + (lane >> 2);
    int dc = (lane & 3) * 2;
    #pragma unroll
    for (int dt = 0; dt < 10; dt++) {
        int d = dt * 8 + dc;
        __half2* p0 = (__half2*)(att + (size_t)r0 * NEMBD + h * HDIM + d);
        __half2* p1 = (__half2*)(att + (size_t)(r0 + 8) * NEMBD + h * HDIM + d);
        *p0 = __floats2half2_rn(oa[dt][0] * inv0, oa[dt][1] * inv0);
        *p1 = __floats2half2_rn(oa[dt][2] * inv1, oa[dt][3] * inv1);
    }
}

// ---------------------------------------------------------------------------
// Launch
// ---------------------------------------------------------------------------
extern "C" void kernel_launch(void* const* d_in, const int* in_sizes, int n_in,
                              void* d_out, int out_size) {
    const float* hidden = (const float*)d_in[0];
    const float* Wqkv_w = (const float*)d_in[1];
    const float* Wqkv_b = (const float*)d_in[2];
    const float* out_w  = (const float*)d_in[3];
    const float* out_b  = (const float*)d_in[4];
    const float* cosT   = (const float*)d_in[5];
    const float* sinT   = (const float*)d_in[6];
    float* out = (float*)d_out;

    float* qkv;
    cudaGetSymbolAddress((void**)&qkv, g_qkv);
    __half *Ha, *Wh, *Wl, *Ca, *Oh, *Ol, *Qh, *Kh, *Vh;
    cudaGetSymbolAddress((void**)&Ha, g_Ha);
    cudaGetSymbolAddress((void**)&Wh, g_Wh); cudaGetSymbolAddress((void**)&Wl, g_Wl);
    cudaGetSymbolAddress((void**)&Ca, g_Ca);
    cudaGetSymbolAddress((void**)&Oh, g_Oh); cudaGetSymbolAddress((void**)&Ol, g_Ol);
    cudaGetSymbolAddress((void**)&Qh, g_Qh);
    cudaGetSymbolAddress((void**)&Kh, g_Kh);
    cudaGetSymbolAddress((void**)&Vh, g_Vh);

    cudaFuncSetAttribute(gemm_fp16, cudaFuncAttributeMaxDynamicSharedMemorySize, GEMM_SMEM);
    cudaFuncSetAttribute(flash_fp16, cudaFuncAttributeMaxDynamicSharedMemorySize, FA_SMEM);

    // Convert inputs
    {
        int n4 = SEQ * NEMBD / 4;
        cvt_trunc<<<(n4 + 255) / 256, 256>>>(hidden, Ha, n4);
        n4 = OPSIZE * NEMBD / 4;
        cvt_split16<<<(n4 + 255) / 256, 256>>>(Wqkv_w, Wh, Wl, n4);
    }

    // 1) QKV = H @ Wqkv^T + b  (HMMA fp16, 2 products)
    {
        dim3 grid(OPSIZE / 128, SEQ / 128);
        gemm_fp16<<<grid, 256, GEMM_SMEM>>>(Ha, Wh, Wl, Wqkv_b, qkv,
                                            SEQ, OPSIZE, NEMBD);
    }

    // 2) RoPE + fp16 pack (head-major)
    {
        int total = SEQ * NHEAD * HDIM;
        rope_pack<<<(total + 255) / 256, 256>>>(qkv, cosT, sinT, Qh, Kh, Vh);
    }

    // 3) HMMA causal flash attention -> fp16 att
    {
        dim3 grid(SEQ / 64, NHEAD);
        flash_fp16<<<grid, 128, FA_SMEM>>>(Qh, Kh, Vh, Ca);
    }

    // 4) out = att @ out_w^T + out_b  (HMMA fp16, 2 products)
    {
        int n4 = NEMBD * NEMBD / 4;
        cvt_split16<<<(n4 + 255) / 256, 256>>>(out_w, Oh, Ol, n4);
        dim3 grid(NEMBD / 128, SEQ / 128);
        gemm_fp16<<<grid, 256, GEMM_SMEM>>>(Ca, Oh, Ol, out_b, out,
                                            SEQ, NEMBD, NEMBD);
    }
}